// round 7
// baseline (speedup 1.0000x reference)
#include <cuda_runtime.h>
#include <cuda_bf16.h>
#include <cstdint>

// out[b] = ||x_b||^2 * (x_b^T rho x_b) = ||x||^2 * (x^T S x),  S=(rho+rho^T)/2
// x = h + l (bf16 split), S = Sh + Sl (bf16 split, both symmetric):
//   q ~= h^T Sl h + h^T Sh (h + 2l)     (2 GEMM terms; dropped terms O(eps^2))
// Grid: 64 M-tiles x 2 N-halves. Cross-CTA combine via atomicAdd + last-CTA.

#define BATCH 4096
#define DIMX 256
#define TILE_M 64
#define TILE_N 128
#define NTHREADS 512
#define NKCHUNKS 4          // K chunks of 64

__device__ __nv_bfloat16 g_Sh[DIMX * DIMX];
__device__ __nv_bfloat16 g_Sl[DIMX * DIMX];
__device__ float g_q[BATCH];
__device__ float g_n[BATCH];
__device__ int   g_cnt[BATCH / TILE_M];

// ---- dynamic smem layout (bytes) ----
#define A_STRIDE 264        // bf16/row (528B pitch; 4i%32 distinct -> conflict-free ldsm)
#define B_STRIDE 72         // bf16/row (144B pitch; conflict-free)
#define SM_AH    0                          // 64 x 264 x2 = 33792
#define SM_AL    33792
#define SM_BH0   67584                      // 128 x 72 x2 = 18432
#define SM_BL0   86016
#define SM_BH1   104448
#define SM_BL1   122880
#define SM_QP    141312                     // float[16][16] = 1024
#define SM_FLAG  142336
#define SMEM_TOTAL 142464

__device__ __forceinline__ uint32_t smem_u32(const void* p) {
    uint32_t a;
    asm("{ .reg .u64 t; cvta.to.shared.u64 t, %1; cvt.u32.u64 %0, t; }"
        : "=r"(a) : "l"(p));
    return a;
}
__device__ __forceinline__ void cp16(uint32_t dst, const void* src) {
    asm volatile("cp.async.cg.shared.global [%0], [%1], 16;" :: "r"(dst), "l"(src));
}
__device__ __forceinline__ void cp_commit() {
    asm volatile("cp.async.commit_group;" ::: "memory");
}
__device__ __forceinline__ void mma16816(float* c, const uint32_t* a, const uint32_t* b) {
    asm volatile(
        "mma.sync.aligned.m16n8k16.row.col.f32.bf16.bf16.f32 "
        "{%0,%1,%2,%3}, {%4,%5,%6,%7}, {%8,%9}, {%0,%1,%2,%3};"
        : "+f"(c[0]), "+f"(c[1]), "+f"(c[2]), "+f"(c[3])
        : "r"(a[0]), "r"(a[1]), "r"(a[2]), "r"(a[3]), "r"(b[0]), "r"(b[1]));
}
__device__ __forceinline__ void ldsm_x4(uint32_t* r, uint32_t addr) {
    asm volatile("ldmatrix.sync.aligned.m8n8.x4.shared.b16 {%0,%1,%2,%3}, [%4];"
                 : "=r"(r[0]), "=r"(r[1]), "=r"(r[2]), "=r"(r[3]) : "r"(addr));
}
__device__ __forceinline__ void split4(const float4 v, uint2& hi, uint2& lo) {
    __nv_bfloat162 h01 = __float22bfloat162_rn(make_float2(v.x, v.y));
    __nv_bfloat162 h23 = __float22bfloat162_rn(make_float2(v.z, v.w));
    float2 f01 = __bfloat1622float2(h01);
    float2 f23 = __bfloat1622float2(h23);
    __nv_bfloat162 l01 = __float22bfloat162_rn(make_float2(v.x - f01.x, v.y - f01.y));
    __nv_bfloat162 l23 = __float22bfloat162_rn(make_float2(v.z - f23.x, v.w - f23.y));
    hi.x = *reinterpret_cast<const uint32_t*>(&h01);
    hi.y = *reinterpret_cast<const uint32_t*>(&h23);
    lo.x = *reinterpret_cast<const uint32_t*>(&l01);
    lo.y = *reinterpret_cast<const uint32_t*>(&l23);
}

// ---- cvt: S = (rho + rho^T)/2, split into bf16 hi/lo ----
__global__ void cvt_sym(const float* __restrict__ R) {
    const int i = blockIdx.x * blockDim.x + threadIdx.x;   // 0..65535
    const int r = i >> 8, c = i & 255;
    const float s = 0.5f * (R[i] + R[c * DIMX + r]);
    const __nv_bfloat16 h = __float2bfloat16(s);
    const __nv_bfloat16 l = __float2bfloat16(s - __bfloat162float(h));
    g_Sh[i] = h;
    g_Sl[i] = l;
}

__global__ __launch_bounds__(NTHREADS, 1)
void qmd_mma(const float* __restrict__ X, float* __restrict__ out) {
    extern __shared__ char smem[];
    const uint32_t sb = smem_u32(smem);
    const int t = threadIdx.x;
    const int wid = t >> 5;
    const int lane = t & 31;

    const int mt = blockIdx.x >> 1;          // M tile 0..63
    const int nh = blockIdx.x & 1;           // N half 0..1
    const int b0 = mt * TILE_M;
    const int ncol0 = nh * TILE_N;           // global col offset of this slab

    const int mg = wid >> 2;                 // 0..3 : 16-row group
    const int ng = wid & 3;                  // 0..3 : 32-col group (slab-local)
    const int n_base = ng * 32;

    // ---- prefetch B chunks 0,1 (Sh/Sl rows ncol0..ncol0+127, K-chunks of 64) ----
    #pragma unroll
    for (int kb = 0; kb < 2; kb++) {
        const uint32_t bh = kb ? SM_BH1 : SM_BH0;
        const uint32_t bl = kb ? SM_BL1 : SM_BL0;
        #pragma unroll
        for (int i = 0; i < 4; i++) {
            const int f = t + i * NTHREADS;          // 0..2047
            const int arr = f >> 10, rem = f & 1023;
            const int n = rem >> 3, c = rem & 7;     // 128 rows x 8 (16B units)
            const uint32_t dst = sb + (arr ? bl : bh) + n * (B_STRIDE * 2) + c * 16;
            const __nv_bfloat16* src = (arr ? g_Sl : g_Sh)
                                       + (size_t)(ncol0 + n) * DIMX + kb * 64 + c * 8;
            cp16(dst, src);
        }
        cp_commit();
    }

    // ---- load + convert A tile: 64 rows x 256 cols, hi/lo (overlaps cp.async) ----
    {
        const float4* __restrict__ Xg = reinterpret_cast<const float4*>(X);
        #pragma unroll
        for (int i = 0; i < 8; i++) {
            const int f = t + i * NTHREADS;          // 0..4095
            const int r = f >> 6, c4 = f & 63;
            float4 v = Xg[(size_t)(b0 + r) * (DIMX / 4) + c4];
            uint2 hi, lo;
            split4(v, hi, lo);
            const uint32_t off = r * (A_STRIDE * 2) + c4 * 8;
            *reinterpret_cast<uint2*>(smem + SM_AH + off) = hi;
            *reinterpret_cast<uint2*>(smem + SM_AL + off) = lo;
        }
    }

    // ldmatrix base addresses
    const int m_idx = lane >> 3;
    const uint32_t a_row = mg * 16 + (m_idx & 1) * 8 + (lane & 7);
    const uint32_t a_base = a_row * (A_STRIDE * 2) + (m_idx >> 1) * 16;
    const uint32_t b_rowpart = (m_idx >> 1) * 8 + (lane & 7);
    const uint32_t b_base0 = (n_base + b_rowpart) * (B_STRIDE * 2) + (m_idx & 1) * 16;
    const uint32_t b_base1 = (n_base + 16 + b_rowpart) * (B_STRIDE * 2) + (m_idx & 1) * 16;

    float acc_a[4][4], acc_b[4][4];
    #pragma unroll
    for (int ni = 0; ni < 4; ni++)
        #pragma unroll
        for (int e = 0; e < 4; e++) { acc_a[ni][e] = 0.0f; acc_b[ni][e] = 0.0f; }

    uint32_t aH[2][4], bH[2][8], bL[2][8];

    for (int kb = 0; kb < NKCHUNKS; kb++) {
        if (kb == NKCHUNKS - 1)
            asm volatile("cp.async.wait_group 0;" ::: "memory");
        else
            asm volatile("cp.async.wait_group 1;" ::: "memory");
        __syncthreads();

        const uint32_t bh = sb + ((kb & 1) ? SM_BH1 : SM_BH0);
        const uint32_t bl = sb + ((kb & 1) ? SM_BL1 : SM_BL0);
        const uint32_t ah = sb + SM_AH + a_base + (kb * 64) * 2;

        ldsm_x4(aH[0], ah);
        ldsm_x4(&bH[0][0], bh + b_base0);
        ldsm_x4(&bH[0][4], bh + b_base1);
        ldsm_x4(&bL[0][0], bl + b_base0);
        ldsm_x4(&bL[0][4], bl + b_base1);

        #pragma unroll
        for (int k16 = 0; k16 < 4; k16++) {
            const int cur = k16 & 1, nxt = cur ^ 1;
            if (k16 < 3) {
                const uint32_t ko = (k16 + 1) * 32;
                ldsm_x4(aH[nxt], ah + ko);
                ldsm_x4(&bH[nxt][0], bh + b_base0 + ko);
                ldsm_x4(&bH[nxt][4], bh + b_base1 + ko);
                ldsm_x4(&bL[nxt][0], bl + b_base0 + ko);
                ldsm_x4(&bL[nxt][4], bl + b_base1 + ko);
            }
            #pragma unroll
            for (int ni = 0; ni < 4; ni++) {
                mma16816(acc_a[ni], aH[cur], &bH[cur][ni * 2]);   // h^T Sh
                mma16816(acc_b[ni], aH[cur], &bL[cur][ni * 2]);   // h^T Sl
            }
        }
        __syncthreads();

        if (kb < NKCHUNKS - 2) {
            const int nk = kb + 2;
            const uint32_t dbh = (kb & 1) ? SM_BH1 : SM_BH0;
            const uint32_t dbl = (kb & 1) ? SM_BL1 : SM_BL0;
            #pragma unroll
            for (int i = 0; i < 4; i++) {
                const int f = t + i * NTHREADS;
                const int arr = f >> 10, rem = f & 1023;
                const int n = rem >> 3, c = rem & 7;
                const uint32_t dst = sb + (arr ? dbl : dbh) + n * (B_STRIDE * 2) + c * 16;
                const __nv_bfloat16* src = (arr ? g_Sl : g_Sh)
                                           + (size_t)(ncol0 + n) * DIMX + nk * 64 + c * 8;
                cp16(dst, src);
            }
            cp_commit();
        }
    }

    // ---- epilogue: q_part = sum_j Za*(h+2l) + Zb*h  over this CTA's N slab ----
    const __nv_bfloat16* sAh = reinterpret_cast<const __nv_bfloat16*>(smem + SM_AH);
    const __nv_bfloat16* sAl = reinterpret_cast<const __nv_bfloat16*>(smem + SM_AL);
    float q[2] = {0, 0};
    #pragma unroll
    for (int ni = 0; ni < 4; ni++) {
        const int j0 = ncol0 + n_base + ni * 8 + (lane & 3) * 2;
        const int r0 = mg * 16 + (lane >> 2);
        #pragma unroll
        for (int e = 0; e < 4; e++) {
            const int r = r0 + (e >> 1) * 8;
            const int j = j0 + (e & 1);
            const float xh = __bfloat162float(sAh[r * A_STRIDE + j]);
            const float xl = __bfloat162float(sAl[r * A_STRIDE + j]);
            const int s = e >> 1;
            q[s] = fmaf(acc_a[ni][e], xh + 2.0f * xl, q[s]);
            q[s] = fmaf(acc_b[ni][e], xh, q[s]);
        }
    }
    #pragma unroll
    for (int off = 1; off <= 2; off <<= 1) {
        q[0] += __shfl_xor_sync(0xffffffffu, q[0], off);
        q[1] += __shfl_xor_sync(0xffffffffu, q[1], off);
    }
    float* qp = reinterpret_cast<float*>(smem + SM_QP);
    if ((lane & 3) == 0) {
        qp[wid * 16 + (lane >> 2)] = q[0];
        qp[wid * 16 + (lane >> 2) + 8] = q[1];
    }

    // ---- n = ||x||^2 (nh==0 CTA only), from smem h+l ----
    if (nh == 0) {
        const int nr = wid * 4 + (lane >> 3);     // 0..63
        const int cg = (lane & 7) * 32;
        float ns = 0.0f;
        #pragma unroll
        for (int c = 0; c < 32; c++) {
            const float xf = __bfloat162float(sAh[nr * A_STRIDE + cg + c]) +
                             __bfloat162float(sAl[nr * A_STRIDE + cg + c]);
            ns = fmaf(xf, xf, ns);
        }
        #pragma unroll
        for (int off = 1; off <= 4; off <<= 1)
            ns += __shfl_xor_sync(0xffffffffu, ns, off);
        if ((lane & 7) == 0) g_n[b0 + nr] = ns;
    }
    __syncthreads();

    // ---- combine across the 2 N-half CTAs ----
    if (t < TILE_M) {
        const int mgf = t >> 4, rloc = t & 15;
        float qs = 0.0f;
        #pragma unroll
        for (int w = 0; w < 4; w++)
            qs += qp[(mgf * 4 + w) * 16 + rloc];
        atomicAdd(&g_q[b0 + t], qs);
        __threadfence();
    }
    __syncthreads();

    int* flag = reinterpret_cast<int*>(smem + SM_FLAG);
    if (t == 0) {
        const int old = atomicAdd(&g_cnt[mt], 1);
        *flag = (old == 1);
    }
    __syncthreads();

    if (*flag) {                               // last CTA of the pair finalizes
        __threadfence();
        if (t < TILE_M) {
            const float qq = *reinterpret_cast<volatile float*>(&g_q[b0 + t]);
            const float nn = *reinterpret_cast<volatile float*>(&g_n[b0 + t]);
            out[b0 + t] = qq * nn;
            g_q[b0 + t] = 0.0f;                // reset for next launch/replay
        }
        if (t == 0) g_cnt[mt] = 0;
    }
}

extern "C" void kernel_launch(void* const* d_in, const int* in_sizes, int n_in,
                              void* d_out, int out_size) {
    const float* X   = (const float*)d_in[0];
    const float* rho = (const float*)d_in[1];
    float* out = (float*)d_out;

    cvt_sym<<<DIMX * DIMX / 256, 256>>>(rho);

    cudaFuncSetAttribute(qmd_mma, cudaFuncAttributeMaxDynamicSharedMemorySize, SMEM_TOTAL);
    qmd_mma<<<(out_size / TILE_M) * 2, NTHREADS, SMEM_TOTAL>>>(X, out);
}